// round 9
// baseline (speedup 1.0000x reference)
#include <cuda_runtime.h>
#include <cuda_bf16.h>
#include <math.h>
#include <stdint.h>

#define N 6144
#define D 128
#define INV_TAU 10.0f
#define NB (2 * N)
#define JSPLIT 12
#define TILES_PER 16   // 12*16*64 = 12288 columns

// ---------------- device scratch ----------------
__device__ float g_Fn[N * D];
__device__ float g_Mn[N * D];
__device__ float g_Pn[N * D];
__device__ __nv_bfloat16 g_Abf[N * D];
__device__ __nv_bfloat16 g_Bbf[NB * D];
__device__ float g_repr[2][N * D];
__device__ float g_rowsum[2][N];
__device__ float g_pos[2][N];
__device__ float g_sumall[2][N];
__device__ float g_weights[N * 2];
__device__ float g_loss_acc;

// ---------------- PTX helpers ----------------
__device__ __forceinline__ uint32_t s2u(const void* p) {
    uint32_t a;
    asm("{ .reg .u64 t; cvta.to.shared.u64 t, %1; cvt.u32.u64 %0, t; }" : "=r"(a) : "l"(p));
    return a;
}
__device__ __forceinline__ void cp16(uint32_t dst, const void* src) {
    asm volatile("cp.async.cg.shared.global [%0], [%1], 16;" :: "r"(dst), "l"(src));
}
#define CP_COMMIT() asm volatile("cp.async.commit_group;")
__device__ __forceinline__ void ldsm4(uint32_t* r, uint32_t addr) {
    asm volatile("ldmatrix.sync.aligned.m8n8.x4.shared.b16 {%0,%1,%2,%3}, [%4];"
                 : "=r"(r[0]), "=r"(r[1]), "=r"(r[2]), "=r"(r[3]) : "r"(addr));
}
__device__ __forceinline__ void mma_bf16(float* d, const uint32_t* a, uint32_t b0, uint32_t b1) {
    asm volatile(
        "mma.sync.aligned.m16n8k16.row.col.f32.bf16.bf16.f32 "
        "{%0,%1,%2,%3}, {%4,%5,%6,%7}, {%8,%9}, {%0,%1,%2,%3};"
        : "+f"(d[0]), "+f"(d[1]), "+f"(d[2]), "+f"(d[3])
        : "r"(a[0]), "r"(a[1]), "r"(a[2]), "r"(a[3]), "r"(b0), "r"(b1));
}

// SMEM tiles (stride 272 B = 128 data + 16 pad -> conflict-free ldmatrix)
#define TSTRIDE 272
#define A_TILE_BYTES (128 * TSTRIDE)   // 34816
#define B_TILE_BYTES (64 * TSTRIDE)    // 17408
static constexpr int OFF_A = 0;
static constexpr int OFF_B = A_TILE_BYTES;
static constexpr int SIMTC_SMEM = A_TILE_BYTES + 2 * B_TILE_BYTES;  // 69632

// ---------------- K0: zero ----------------
__global__ void k_zero() {
    int idx = blockIdx.x * blockDim.x + threadIdx.x;
    if (idx < 2 * N) g_sumall[idx / N][idx % N] = 0.0f;
    if (idx == 0) g_loss_acc = 0.0f;
}

// ---------------- K1: normalize + bf16 cast ----------------
__global__ void k_normalize(const float* __restrict__ embF,
                            const float* __restrict__ embM,
                            const float* __restrict__ embP) {
    int i = blockIdx.x;
    int which = blockIdx.y;
    const float* src = (which == 0) ? embF : (which == 1) ? embM : embP;
    float* dst = (which == 0) ? g_Fn : (which == 1) ? g_Mn : g_Pn;
    int t = threadIdx.x;  // 128
    float v = src[(size_t)i * D + t];
    __shared__ float red[128];
    red[t] = v * v;
    __syncthreads();
#pragma unroll
    for (int s = 64; s > 0; s >>= 1) {
        if (t < s) red[t] += red[t + s];
        __syncthreads();
    }
    float norm = fmaxf(sqrtf(red[0]), 1e-12f);
    float nv = v / norm;
    dst[(size_t)i * D + t] = nv;
    __nv_bfloat16 h = __float2bfloat16(nv);
    if (which == 0) g_Abf[i * D + t] = h;
    else g_Bbf[((which == 1) ? i : (N + i)) * D + t] = h;
}

// ---------------- K2: adjacency scan (256 thr, warp-specialized epilogue) ----
#define MAXNZ 768
#define VPT 6  // (N/4)/256 float4 per thread
__global__ __launch_bounds__(256) void k_repr_pos(
    const float* __restrict__ FM_adj, const float* __restrict__ FP_adj,
    const float* __restrict__ embM, const float* __restrict__ embP) {
    int i = blockIdx.x;
    int w = blockIdx.y;
    const float* adj = (w == 0) ? FM_adj : FP_adj;
    const float* emb = (w == 0) ? embM : embP;
    const float* nrm = (w == 0) ? g_Mn : g_Pn;
    int t = threadIdx.x;
    int lane = t & 31;
    int warp = t >> 5;

    __shared__ int s_idx[MAXNZ];
    __shared__ float s_val[MAXNZ];
    __shared__ int s_cnt;
    __shared__ float s_rowsum;
    __shared__ float s_pos;
    __shared__ float s_F[D];

    if (t == 0) { s_cnt = 0; s_rowsum = 0.0f; s_pos = 0.0f; }
    if (t < D) s_F[t] = g_Fn[(size_t)i * D + t];

    const float4* arow = (const float4*)(adj + (size_t)i * N);
    float4 v[VPT];
#pragma unroll
    for (int q = 0; q < VPT; ++q) v[q] = __ldcs(&arow[t + q * 256]);
    __syncthreads();  // init visible before atomics

    // local count + sum
    int nloc = 0;
    float myrs = 0.0f;
#pragma unroll
    for (int q = 0; q < VPT; ++q) {
        float comp[4] = {v[q].x, v[q].y, v[q].z, v[q].w};
#pragma unroll
        for (int e = 0; e < 4; ++e) {
            if (comp[e] != 0.0f) { ++nloc; myrs += comp[e]; }
        }
    }
    // warp inclusive scan -> 1 atomic per warp
    int inc = nloc;
#pragma unroll
    for (int o = 1; o < 32; o <<= 1) {
        int u = __shfl_up_sync(0xffffffffu, inc, o);
        if (lane >= o) inc += u;
    }
    int wtot = __shfl_sync(0xffffffffu, inc, 31);
    int base = 0;
    if (lane == 31) base = atomicAdd(&s_cnt, wtot);
    base = __shfl_sync(0xffffffffu, base, 31);
    int p = base + inc - nloc;
#pragma unroll
    for (int q = 0; q < VPT; ++q) {
        int c = t + q * 256;
        float comp[4] = {v[q].x, v[q].y, v[q].z, v[q].w};
#pragma unroll
        for (int e = 0; e < 4; ++e) {
            float x = comp[e];
            if (x != 0.0f) {
                if (p < MAXNZ) { s_idx[p] = c * 4 + e; s_val[p] = x; }
                ++p;
            }
        }
    }
#pragma unroll
    for (int o = 16; o; o >>= 1) myrs += __shfl_xor_sync(0xffffffffu, myrs, o);
    if (lane == 0) atomicAdd(&s_rowsum, myrs);
    __syncthreads();

    int cnt = min(s_cnt, MAXNZ);
    float rs = s_rowsum;
    float denom = fmaxf(rs, 1.0f);

    if (warp < 4) {
        // warps 0-3: repr gather, thread t = dim
        float a0 = 0, a1 = 0, a2 = 0, a3 = 0;
        int e = 0;
        for (; e + 4 <= cnt; e += 4) {
            a0 += s_val[e + 0] * emb[(size_t)s_idx[e + 0] * D + t];
            a1 += s_val[e + 1] * emb[(size_t)s_idx[e + 1] * D + t];
            a2 += s_val[e + 2] * emb[(size_t)s_idx[e + 2] * D + t];
            a3 += s_val[e + 3] * emb[(size_t)s_idx[e + 3] * D + t];
        }
        for (; e < cnt; ++e) a0 += s_val[e] * emb[(size_t)s_idx[e] * D + t];
        g_repr[w][(size_t)i * D + t] = ((a0 + a1) + (a2 + a3)) / denom;
    } else {
        // warps 4-7: pos dot products
        float lp = 0.0f;
        for (int q = warp - 4; q < cnt; q += 4) {
            int j = s_idx[q];
            const float* nr = nrm + (size_t)j * D;
            float pd = s_F[lane] * nr[lane]
                     + s_F[lane + 32] * nr[lane + 32]
                     + s_F[lane + 64] * nr[lane + 64]
                     + s_F[lane + 96] * nr[lane + 96];
#pragma unroll
            for (int o = 16; o; o >>= 1) pd += __shfl_xor_sync(0xffffffffu, pd, o);
            if (lane == 0) lp += s_val[q] * __expf(pd * INV_TAU);
        }
        if (lane == 0) atomicAdd(&s_pos, lp);
    }
    __syncthreads();
    if (t == 0) { g_rowsum[w][i] = rs; g_pos[w][i] = s_pos; }
}

// ---------------- K3: bf16 HMMA sim row sums (BN=64, spill-free) ----------------
__device__ __forceinline__ void load_tileA(uint32_t dst, const __nv_bfloat16* src,
                                           int row0, int tid) {
#pragma unroll
    for (int p = 0; p < 8; ++p) {
        int idx = tid + (p << 8);
        int r = idx >> 4, c = idx & 15;
        cp16(dst + r * TSTRIDE + c * 16, src + (size_t)(row0 + r) * D + c * 8);
    }
}
__device__ __forceinline__ void load_tileB(uint32_t dst, const __nv_bfloat16* src,
                                           int row0, int tid) {
#pragma unroll
    for (int p = 0; p < 4; ++p) {
        int idx = tid + (p << 8);
        int r = idx >> 4, c = idx & 15;
        cp16(dst + r * TSTRIDE + c * 16, src + (size_t)(row0 + r) * D + c * 8);
    }
}

__global__ __launch_bounds__(256, 2) void k_simsum_mma() {
    extern __shared__ __align__(16) char dsm[];
    const uint32_t smb = s2u(dsm);
    const int tid = threadIdx.x;
    const int wid = tid >> 5;
    const int lane = tid & 31;
    const int wm = (wid & 3) * 32;
    const int wn = (wid >> 2) * 32;
    const int i0 = blockIdx.x * 128;
    const int tbase = blockIdx.y * TILES_PER;
    const int tgt = (blockIdx.y < JSPLIT / 2) ? 0 : 1;

    const uint32_t aoff = (uint32_t)(lane & 15) * TSTRIDE + (uint32_t)(lane >> 4) * 16;
    const uint32_t boff = (uint32_t)(((lane >> 3) & 1) * 8 + (lane & 7)) * TSTRIDE
                        + (uint32_t)(lane >> 4) * 16;

    load_tileA(smb + OFF_A, g_Abf, i0, tid);
    load_tileB(smb + OFF_B, g_Bbf, tbase * 64, tid);
    CP_COMMIT();
    load_tileB(smb + OFF_B + B_TILE_BYTES, g_Bbf, (tbase + 1) * 64, tid);
    CP_COMMIT();

    float rsum[2][2] = {{0, 0}, {0, 0}};

    for (int t = 0; t < TILES_PER; ++t) {
        const int buf = t & 1;
        asm volatile("cp.async.wait_group 1;");
        __syncthreads();

        const uint32_t bb = smb + OFF_B + buf * B_TILE_BYTES;

        float acc[2][4][4];
#pragma unroll
        for (int f = 0; f < 2; ++f)
#pragma unroll
            for (int n = 0; n < 4; ++n)
#pragma unroll
                for (int r = 0; r < 4; ++r) acc[f][n][r] = 0.0f;

#pragma unroll
        for (int ks = 0; ks < 8; ++ks) {
            uint32_t ah[2][4];
#pragma unroll
            for (int f = 0; f < 2; ++f)
                ldsm4(ah[f], smb + OFF_A + (wm + f * 16) * TSTRIDE + ks * 32 + aoff);
#pragma unroll
            for (int g = 0; g < 2; ++g) {
                uint32_t bh[4];
                ldsm4(bh, bb + (wn + g * 16) * TSTRIDE + ks * 32 + boff);
#pragma unroll
                for (int f = 0; f < 2; ++f) {
                    mma_bf16(acc[f][2 * g], ah[f], bh[0], bh[2]);
                    mma_bf16(acc[f][2 * g + 1], ah[f], bh[1], bh[3]);
                }
            }
        }

        __syncthreads();
        if (t + 2 < TILES_PER)
            load_tileB(smb + OFF_B + buf * B_TILE_BYTES, g_Bbf, (tbase + t + 2) * 64, tid);
        CP_COMMIT();

#pragma unroll
        for (int f = 0; f < 2; ++f) {
            float e0 = 0.0f, e1 = 0.0f;
#pragma unroll
            for (int n = 0; n < 4; ++n) {
                e0 += __expf(acc[f][n][0] * INV_TAU) + __expf(acc[f][n][1] * INV_TAU);
                e1 += __expf(acc[f][n][2] * INV_TAU) + __expf(acc[f][n][3] * INV_TAU);
            }
            rsum[f][0] += e0;
            rsum[f][1] += e1;
        }
    }

#pragma unroll
    for (int f = 0; f < 2; ++f)
#pragma unroll
        for (int r = 0; r < 2; ++r) {
            float v = rsum[f][r];
            v += __shfl_xor_sync(0xffffffffu, v, 1);
            v += __shfl_xor_sync(0xffffffffu, v, 2);
            if ((lane & 3) == 0) {
                int row = i0 + wm + f * 16 + (lane >> 2) + r * 8;
                atomicAdd(&g_sumall[tgt][row], v);
            }
        }
}

// ---------------- K4: MLP + softmax (W1 from L2, feats-only smem) ----------------
#define MLP_ROWS 48
#define FSTR 257
#define MLP_SMEM ((MLP_ROWS * FSTR) * (int)sizeof(float))  // 49344
__global__ __launch_bounds__(256) void k_mlp(const float* __restrict__ W1,
                                             const float* __restrict__ b1,
                                             const float* __restrict__ W2,
                                             const float* __restrict__ b2,
                                             float* __restrict__ out_weights) {
    extern __shared__ float feats[];  // [48][FSTR]

    const int tid = threadIdx.x;
    const int lane = tid & 31;
    const int wp = tid >> 5;
    const int i0 = blockIdx.x * MLP_ROWS;

#pragma unroll
    for (int p = 0; p < MLP_ROWS; ++p) {
        int s = tid + p * 256;
        int r = s >> 8, k = s & 255;
        feats[r * FSTR + k] = (k < 128) ? g_repr[0][(size_t)(i0 + r) * D + k]
                                        : g_repr[1][(size_t)(i0 + r) * D + (k - 128)];
    }
    __syncthreads();

    const int c4 = lane;
    const float4* W1v = (const float4*)W1;  // [256][32] float4
    const float4 b1v = ((const float4*)b1)[c4];
    const float4 w2a = ((const float4*)W2)[2 * c4];
    const float4 w2b = ((const float4*)W2)[2 * c4 + 1];
    const int r0 = wp * 6;

    float acc[6][4];
#pragma unroll
    for (int r = 0; r < 6; ++r)
#pragma unroll
        for (int q = 0; q < 4; ++q) acc[r][q] = 0.0f;

    float4 wv = __ldg(&W1v[c4]);
#pragma unroll 4
    for (int k = 0; k < 256; ++k) {
        float4 nv;
        if (k < 255) nv = __ldg(&W1v[(k + 1) * 32 + c4]);
#pragma unroll
        for (int r = 0; r < 6; ++r) {
            float f = feats[(r0 + r) * FSTR + k];
            acc[r][0] = fmaf(f, wv.x, acc[r][0]);
            acc[r][1] = fmaf(f, wv.y, acc[r][1]);
            acc[r][2] = fmaf(f, wv.z, acc[r][2]);
            acc[r][3] = fmaf(f, wv.w, acc[r][3]);
        }
        wv = nv;
    }

#pragma unroll
    for (int r = 0; r < 6; ++r) {
        float h0 = fmaxf(acc[r][0] + b1v.x, 0.0f);
        float h1 = fmaxf(acc[r][1] + b1v.y, 0.0f);
        float h2 = fmaxf(acc[r][2] + b1v.z, 0.0f);
        float h3 = fmaxf(acc[r][3] + b1v.w, 0.0f);
        float p0 = h0 * w2a.x + h1 * w2a.z + h2 * w2b.x + h3 * w2b.z;
        float p1 = h0 * w2a.y + h1 * w2a.w + h2 * w2b.y + h3 * w2b.w;
#pragma unroll
        for (int o = 16; o; o >>= 1) {
            p0 += __shfl_xor_sync(0xffffffffu, p0, o);
            p1 += __shfl_xor_sync(0xffffffffu, p1, o);
        }
        if (lane == 0) {
            int row = i0 + r0 + r;
            float o0 = p0 + b2[0];
            float o1 = p1 + b2[1];
            float mx = fmaxf(o0, o1);
            float e0 = expf(o0 - mx), e1 = expf(o1 - mx);
            float inv = 1.0f / (e0 + e1);
            float w0 = e0 * inv, w1 = e1 * inv;
            g_weights[2 * row] = w0;
            g_weights[2 * row + 1] = w1;
            out_weights[2 * row] = w0;
            out_weights[2 * row + 1] = w1;
        }
    }
}

// ---------------- K5: loss ----------------
__global__ __launch_bounds__(256) void k_loss() {
    int idx = blockIdx.x * blockDim.x + threadIdx.x;
    int stride = gridDim.x * blockDim.x;
    float term = 0.0f;
    for (int i = idx; i < N; i += stride) {
        float w0 = g_weights[2 * i], w1 = g_weights[2 * i + 1];
        float pm = g_pos[0][i], pp = g_pos[1][i];
        float sm = g_sumall[0][i], sp = g_sumall[1][i];
        float wpv = w0 * pm + w1 * pp;
        float wn = w0 * (sm - pm) + w1 * (sp - pp);
        float nei = fmaxf(g_rowsum[0][i] + g_rowsum[1][i], 1.0f);
        float ratio = wpv / (wpv + wn) / nei;
        ratio = fmaxf(ratio, 1e-10f);
        term += -logf(ratio);
    }
    __shared__ float red[256];
    red[threadIdx.x] = term;
    __syncthreads();
#pragma unroll
    for (int s = 128; s > 0; s >>= 1) {
        if (threadIdx.x < s) red[threadIdx.x] += red[threadIdx.x + s];
        __syncthreads();
    }
    if (threadIdx.x == 0) atomicAdd(&g_loss_acc, red[0]);
}

__global__ void k_finalize(float* __restrict__ out) {
    out[0] = g_loss_acc / (float)N;
}

// ---------------- launch (fork-join overlap) ----------------
extern "C" void kernel_launch(void* const* d_in, const int* in_sizes, int n_in,
                              void* d_out, int out_size) {
    const float* embF = (const float*)d_in[0];
    const float* embM = (const float*)d_in[1];
    const float* embP = (const float*)d_in[2];
    const float* FM_adj = (const float*)d_in[3];
    const float* FP_adj = (const float*)d_in[4];
    const float* W1 = (const float*)d_in[5];
    const float* b1 = (const float*)d_in[6];
    const float* W2 = (const float*)d_in[7];
    const float* b2 = (const float*)d_in[8];
    float* out = (float*)d_out;

    static cudaStream_t s1 = nullptr;
    static cudaEvent_t evA = nullptr, evB = nullptr;
    static bool attr_set = false;
    if (!attr_set) {
        cudaStreamCreateWithFlags(&s1, cudaStreamNonBlocking);
        cudaEventCreateWithFlags(&evA, cudaEventDisableTiming);
        cudaEventCreateWithFlags(&evB, cudaEventDisableTiming);
        cudaFuncSetAttribute(k_simsum_mma, cudaFuncAttributeMaxDynamicSharedMemorySize, SIMTC_SMEM);
        cudaFuncSetAttribute(k_mlp, cudaFuncAttributeMaxDynamicSharedMemorySize, MLP_SMEM);
        attr_set = true;
    }

    k_zero<<<(2 * N + 255) / 256, 256>>>();
    k_normalize<<<dim3(N, 3), 128>>>(embF, embM, embP);
    cudaEventRecord(evA, 0);

    // main branch: tensor-core sim sums
    k_simsum_mma<<<dim3(N / 128, JSPLIT), 256, SIMTC_SMEM>>>();

    // side branch: adjacency scan + MLP (DRAM-bound; overlaps tensor work)
    cudaStreamWaitEvent(s1, evA, 0);
    k_repr_pos<<<dim3(N, 2), 256, 0, s1>>>(FM_adj, FP_adj, embM, embP);
    k_mlp<<<N / MLP_ROWS, 256, MLP_SMEM, s1>>>(W1, b1, W2, b2, out + 1);
    cudaEventRecord(evB, s1);

    cudaStreamWaitEvent(0, evB, 0);
    k_loss<<<24, 256>>>();
    k_finalize<<<1, 1>>>(out);
}

// round 10
// speedup vs baseline: 1.0760x; 1.0760x over previous
#include <cuda_runtime.h>
#include <cuda_bf16.h>
#include <math.h>
#include <stdint.h>

#define N 6144
#define D 128
#define INV_TAU 10.0f
#define NB (2 * N)
#define JSPLIT 12
#define TILES_PER 16   // 12*16*64 = 12288 columns
#define GMAX 128       // per-row nonzero cap (mean ~31, 12+ sigma headroom)

// ---------------- device scratch ----------------
__device__ float g_Fn[N * D];
__device__ float g_Mn[N * D];
__device__ float g_Pn[N * D];
__device__ __nv_bfloat16 g_Abf[N * D];
__device__ __nv_bfloat16 g_Bbf[NB * D];
__device__ float g_repr[2][N * D];
__device__ float g_rowsum[2][N];
__device__ float g_pos[2][N];
__device__ float g_sumall[2][N];
__device__ float g_weights[N * 2];
__device__ float g_loss_acc;
__device__ int   g_cnt[2][N];
__device__ int   g_lidx[2][N][GMAX];
__device__ float g_lval[2][N][GMAX];

// ---------------- PTX helpers ----------------
__device__ __forceinline__ uint32_t s2u(const void* p) {
    uint32_t a;
    asm("{ .reg .u64 t; cvta.to.shared.u64 t, %1; cvt.u32.u64 %0, t; }" : "=r"(a) : "l"(p));
    return a;
}
__device__ __forceinline__ void cp16(uint32_t dst, const void* src) {
    asm volatile("cp.async.cg.shared.global [%0], [%1], 16;" :: "r"(dst), "l"(src));
}
#define CP_COMMIT() asm volatile("cp.async.commit_group;")
__device__ __forceinline__ void ldsm4(uint32_t* r, uint32_t addr) {
    asm volatile("ldmatrix.sync.aligned.m8n8.x4.shared.b16 {%0,%1,%2,%3}, [%4];"
                 : "=r"(r[0]), "=r"(r[1]), "=r"(r[2]), "=r"(r[3]) : "r"(addr));
}
__device__ __forceinline__ void mma_bf16(float* d, const uint32_t* a, uint32_t b0, uint32_t b1) {
    asm volatile(
        "mma.sync.aligned.m16n8k16.row.col.f32.bf16.bf16.f32 "
        "{%0,%1,%2,%3}, {%4,%5,%6,%7}, {%8,%9}, {%0,%1,%2,%3};"
        : "+f"(d[0]), "+f"(d[1]), "+f"(d[2]), "+f"(d[3])
        : "r"(a[0]), "r"(a[1]), "r"(a[2]), "r"(a[3]), "r"(b0), "r"(b1));
}

// SMEM tiles (stride 272 B = 128 data + 16 pad -> conflict-free ldmatrix)
#define TSTRIDE 272
#define A_TILE_BYTES (128 * TSTRIDE)
#define B_TILE_BYTES (64 * TSTRIDE)
static constexpr int OFF_A = 0;
static constexpr int OFF_B = A_TILE_BYTES;
static constexpr int SIMTC_SMEM = A_TILE_BYTES + 2 * B_TILE_BYTES;  // 69632

// ---------------- K0: zero ----------------
__global__ void k_zero() {
    int idx = blockIdx.x * blockDim.x + threadIdx.x;
    if (idx < 2 * N) {
        g_sumall[idx / N][idx % N] = 0.0f;
        g_cnt[idx / N][idx % N] = 0;
    }
    if (idx == 0) g_loss_acc = 0.0f;
}

// ---------------- K1: normalize + bf16 cast ----------------
__global__ void k_normalize(const float* __restrict__ embF,
                            const float* __restrict__ embM,
                            const float* __restrict__ embP) {
    int i = blockIdx.x;
    int which = blockIdx.y;
    const float* src = (which == 0) ? embF : (which == 1) ? embM : embP;
    float* dst = (which == 0) ? g_Fn : (which == 1) ? g_Mn : g_Pn;
    int t = threadIdx.x;  // 128
    float v = src[(size_t)i * D + t];
    __shared__ float red[128];
    red[t] = v * v;
    __syncthreads();
#pragma unroll
    for (int s = 64; s > 0; s >>= 1) {
        if (t < s) red[t] += red[t + s];
        __syncthreads();
    }
    float norm = fmaxf(sqrtf(red[0]), 1e-12f);
    float nv = v / norm;
    dst[(size_t)i * D + t] = nv;
    __nv_bfloat16 h = __float2bfloat16(nv);
    if (which == 0) g_Abf[i * D + t] = h;
    else g_Bbf[((which == 1) ? i : (N + i)) * D + t] = h;
}

// ---------------- K2a: pure adjacency stream -> lists + rowsums ----------------
// One block per row i, both matrices. Unconditional rowsum adds (zeros free),
// rare nonzero path pushes to global per-row lists.
__global__ __launch_bounds__(256) void k_scan(const float* __restrict__ FM_adj,
                                              const float* __restrict__ FP_adj) {
    const int i = blockIdx.x;
    const int t = threadIdx.x;
    const int lane = t & 31;
    __shared__ float sF, sP;
    if (t == 0) { sF = 0.0f; sP = 0.0f; }
    __syncthreads();

    const float4* fm = (const float4*)(FM_adj + (size_t)i * N);
    const float4* fp = (const float4*)(FP_adj + (size_t)i * N);

    float rsF = 0.0f, rsP = 0.0f;
#pragma unroll
    for (int q = 0; q < 6; ++q) {
        int c = t + q * 256;
        float4 a = __ldcs(&fm[c]);
        float4 b = __ldcs(&fp[c]);
        rsF += (a.x + a.y) + (a.z + a.w);
        rsP += (b.x + b.y) + (b.z + b.w);
        float ca[4] = {a.x, a.y, a.z, a.w};
        float cb[4] = {b.x, b.y, b.z, b.w};
#pragma unroll
        for (int e = 0; e < 4; ++e) {
            if (ca[e] != 0.0f) {
                int p = atomicAdd(&g_cnt[0][i], 1);
                if (p < GMAX) { g_lidx[0][i][p] = c * 4 + e; g_lval[0][i][p] = ca[e]; }
            }
            if (cb[e] != 0.0f) {
                int p = atomicAdd(&g_cnt[1][i], 1);
                if (p < GMAX) { g_lidx[1][i][p] = c * 4 + e; g_lval[1][i][p] = cb[e]; }
            }
        }
    }
#pragma unroll
    for (int o = 16; o; o >>= 1) {
        rsF += __shfl_xor_sync(0xffffffffu, rsF, o);
        rsP += __shfl_xor_sync(0xffffffffu, rsP, o);
    }
    if (lane == 0) { atomicAdd(&sF, rsF); atomicAdd(&sP, rsP); }
    __syncthreads();
    if (t == 0) { g_rowsum[0][i] = sF; g_rowsum[1][i] = sP; }
}

// ---------------- K2b: gather from lists -> repr + pos (L2-bound) ----------------
__global__ __launch_bounds__(128) void k_gather(const float* __restrict__ embM,
                                                const float* __restrict__ embP) {
    const int i = blockIdx.x;
    const int w = blockIdx.y;
    const float* emb = (w == 0) ? embM : embP;
    const float* nrm = (w == 0) ? g_Mn : g_Pn;
    const int t = threadIdx.x;
    const int lane = t & 31;
    const int warp = t >> 5;

    __shared__ int s_idx[GMAX];
    __shared__ float s_val[GMAX];
    __shared__ float s_F[D];
    __shared__ float s_pos;

    const int cnt = min(g_cnt[w][i], GMAX);
    s_F[t] = g_Fn[(size_t)i * D + t];
    if (t == 0) s_pos = 0.0f;
    if (t < cnt) { s_idx[t] = g_lidx[w][i][t]; s_val[t] = g_lval[w][i][t]; }
    __syncthreads();

    const float denom = fmaxf(g_rowsum[w][i], 1.0f);

    // repr: thread t = dim, 4 accumulation chains (emb rows are L2 hits)
    float a0 = 0, a1 = 0, a2 = 0, a3 = 0;
    int e = 0;
    for (; e + 4 <= cnt; e += 4) {
        a0 += s_val[e + 0] * emb[(size_t)s_idx[e + 0] * D + t];
        a1 += s_val[e + 1] * emb[(size_t)s_idx[e + 1] * D + t];
        a2 += s_val[e + 2] * emb[(size_t)s_idx[e + 2] * D + t];
        a3 += s_val[e + 3] * emb[(size_t)s_idx[e + 3] * D + t];
    }
    for (; e < cnt; ++e) a0 += s_val[e] * emb[(size_t)s_idx[e] * D + t];
    g_repr[w][(size_t)i * D + t] = ((a0 + a1) + (a2 + a3)) / denom;

    // pos: warp-per-entry dot products
    float lp = 0.0f;
    for (int q = warp; q < cnt; q += 4) {
        int j = s_idx[q];
        const float* nr = nrm + (size_t)j * D;
        float pd = s_F[lane] * nr[lane]
                 + s_F[lane + 32] * nr[lane + 32]
                 + s_F[lane + 64] * nr[lane + 64]
                 + s_F[lane + 96] * nr[lane + 96];
#pragma unroll
        for (int o = 16; o; o >>= 1) pd += __shfl_xor_sync(0xffffffffu, pd, o);
        if (lane == 0) lp += s_val[q] * __expf(pd * INV_TAU);
    }
    if (lane == 0) atomicAdd(&s_pos, lp);
    __syncthreads();
    if (t == 0) g_pos[w][i] = s_pos;
}

// ---------------- K3: bf16 HMMA sim row sums (BN=64) ----------------
__device__ __forceinline__ void load_tileA(uint32_t dst, const __nv_bfloat16* src,
                                           int row0, int tid) {
#pragma unroll
    for (int p = 0; p < 8; ++p) {
        int idx = tid + (p << 8);
        int r = idx >> 4, c = idx & 15;
        cp16(dst + r * TSTRIDE + c * 16, src + (size_t)(row0 + r) * D + c * 8);
    }
}
__device__ __forceinline__ void load_tileB(uint32_t dst, const __nv_bfloat16* src,
                                           int row0, int tid) {
#pragma unroll
    for (int p = 0; p < 4; ++p) {
        int idx = tid + (p << 8);
        int r = idx >> 4, c = idx & 15;
        cp16(dst + r * TSTRIDE + c * 16, src + (size_t)(row0 + r) * D + c * 8);
    }
}

__global__ __launch_bounds__(256, 2) void k_simsum_mma() {
    extern __shared__ __align__(16) char dsm[];
    const uint32_t smb = s2u(dsm);
    const int tid = threadIdx.x;
    const int wid = tid >> 5;
    const int lane = tid & 31;
    const int wm = (wid & 3) * 32;
    const int wn = (wid >> 2) * 32;
    const int i0 = blockIdx.x * 128;
    const int tbase = blockIdx.y * TILES_PER;
    const int tgt = (blockIdx.y < JSPLIT / 2) ? 0 : 1;

    const uint32_t aoff = (uint32_t)(lane & 15) * TSTRIDE + (uint32_t)(lane >> 4) * 16;
    const uint32_t boff = (uint32_t)(((lane >> 3) & 1) * 8 + (lane & 7)) * TSTRIDE
                        + (uint32_t)(lane >> 4) * 16;

    load_tileA(smb + OFF_A, g_Abf, i0, tid);
    load_tileB(smb + OFF_B, g_Bbf, tbase * 64, tid);
    CP_COMMIT();
    load_tileB(smb + OFF_B + B_TILE_BYTES, g_Bbf, (tbase + 1) * 64, tid);
    CP_COMMIT();

    float rsum[2][2] = {{0, 0}, {0, 0}};

    for (int t = 0; t < TILES_PER; ++t) {
        const int buf = t & 1;
        asm volatile("cp.async.wait_group 1;");
        __syncthreads();

        const uint32_t bb = smb + OFF_B + buf * B_TILE_BYTES;

        float acc[2][4][4];
#pragma unroll
        for (int f = 0; f < 2; ++f)
#pragma unroll
            for (int n = 0; n < 4; ++n)
#pragma unroll
                for (int r = 0; r < 4; ++r) acc[f][n][r] = 0.0f;

#pragma unroll
        for (int ks = 0; ks < 8; ++ks) {
            uint32_t ah[2][4];
#pragma unroll
            for (int f = 0; f < 2; ++f)
                ldsm4(ah[f], smb + OFF_A + (wm + f * 16) * TSTRIDE + ks * 32 + aoff);
#pragma unroll
            for (int g = 0; g < 2; ++g) {
                uint32_t bh[4];
                ldsm4(bh, bb + (wn + g * 16) * TSTRIDE + ks * 32 + boff);
#pragma unroll
                for (int f = 0; f < 2; ++f) {
                    mma_bf16(acc[f][2 * g], ah[f], bh[0], bh[2]);
                    mma_bf16(acc[f][2 * g + 1], ah[f], bh[1], bh[3]);
                }
            }
        }

        __syncthreads();
        if (t + 2 < TILES_PER)
            load_tileB(smb + OFF_B + buf * B_TILE_BYTES, g_Bbf, (tbase + t + 2) * 64, tid);
        CP_COMMIT();

#pragma unroll
        for (int f = 0; f < 2; ++f) {
            float e0 = 0.0f, e1 = 0.0f;
#pragma unroll
            for (int n = 0; n < 4; ++n) {
                e0 += __expf(acc[f][n][0] * INV_TAU) + __expf(acc[f][n][1] * INV_TAU);
                e1 += __expf(acc[f][n][2] * INV_TAU) + __expf(acc[f][n][3] * INV_TAU);
            }
            rsum[f][0] += e0;
            rsum[f][1] += e1;
        }
    }

#pragma unroll
    for (int f = 0; f < 2; ++f)
#pragma unroll
        for (int r = 0; r < 2; ++r) {
            float v = rsum[f][r];
            v += __shfl_xor_sync(0xffffffffu, v, 1);
            v += __shfl_xor_sync(0xffffffffu, v, 2);
            if ((lane & 3) == 0) {
                int row = i0 + wm + f * 16 + (lane >> 2) + r * 8;
                atomicAdd(&g_sumall[tgt][row], v);
            }
        }
}

// ---------------- K4: MLP + softmax (384 blocks, 2 rows/warp) ----------------
#define MLP_ROWS 16
#define FSTR 257
#define MLP_SMEM ((MLP_ROWS * FSTR) * (int)sizeof(float))  // 16448
__global__ __launch_bounds__(256) void k_mlp(const float* __restrict__ W1,
                                             const float* __restrict__ b1,
                                             const float* __restrict__ W2,
                                             const float* __restrict__ b2,
                                             float* __restrict__ out_weights) {
    extern __shared__ float feats[];  // [16][FSTR]

    const int tid = threadIdx.x;
    const int lane = tid & 31;
    const int wp = tid >> 5;
    const int i0 = blockIdx.x * MLP_ROWS;

#pragma unroll
    for (int p = 0; p < MLP_ROWS; ++p) {
        int s = tid + p * 256;
        int r = s >> 8, k = s & 255;
        feats[r * FSTR + k] = (k < 128) ? g_repr[0][(size_t)(i0 + r) * D + k]
                                        : g_repr[1][(size_t)(i0 + r) * D + (k - 128)];
    }
    __syncthreads();

    const int c4 = lane;
    const float4* W1v = (const float4*)W1;  // [256][32] float4
    const float4 b1v = ((const float4*)b1)[c4];
    const float4 w2a = ((const float4*)W2)[2 * c4];
    const float4 w2b = ((const float4*)W2)[2 * c4 + 1];
    const int r0 = wp * 2;  // 8 warps * 2 rows = 16

    float acc[2][4];
#pragma unroll
    for (int r = 0; r < 2; ++r)
#pragma unroll
        for (int q = 0; q < 4; ++q) acc[r][q] = 0.0f;

    float4 wv = __ldg(&W1v[c4]);
#pragma unroll 4
    for (int k = 0; k < 256; ++k) {
        float4 nv;
        if (k < 255) nv = __ldg(&W1v[(k + 1) * 32 + c4]);
#pragma unroll
        for (int r = 0; r < 2; ++r) {
            float f = feats[(r0 + r) * FSTR + k];
            acc[r][0] = fmaf(f, wv.x, acc[r][0]);
            acc[r][1] = fmaf(f, wv.y, acc[r][1]);
            acc[r][2] = fmaf(f, wv.z, acc[r][2]);
            acc[r][3] = fmaf(f, wv.w, acc[r][3]);
        }
        wv = nv;
    }

#pragma unroll
    for (int r = 0; r < 2; ++r) {
        float h0 = fmaxf(acc[r][0] + b1v.x, 0.0f);
        float h1 = fmaxf(acc[r][1] + b1v.y, 0.0f);
        float h2 = fmaxf(acc[r][2] + b1v.z, 0.0f);
        float h3 = fmaxf(acc[r][3] + b1v.w, 0.0f);
        float p0 = h0 * w2a.x + h1 * w2a.z + h2 * w2b.x + h3 * w2b.z;
        float p1 = h0 * w2a.y + h1 * w2a.w + h2 * w2b.y + h3 * w2b.w;
#pragma unroll
        for (int o = 16; o; o >>= 1) {
            p0 += __shfl_xor_sync(0xffffffffu, p0, o);
            p1 += __shfl_xor_sync(0xffffffffu, p1, o);
        }
        if (lane == 0) {
            int row = i0 + r0 + r;
            float o0 = p0 + b2[0];
            float o1 = p1 + b2[1];
            float mx = fmaxf(o0, o1);
            float e0 = expf(o0 - mx), e1 = expf(o1 - mx);
            float inv = 1.0f / (e0 + e1);
            float w0 = e0 * inv, w1 = e1 * inv;
            g_weights[2 * row] = w0;
            g_weights[2 * row + 1] = w1;
            out_weights[2 * row] = w0;
            out_weights[2 * row + 1] = w1;
        }
    }
}

// ---------------- K5: loss ----------------
__global__ __launch_bounds__(256) void k_loss() {
    int idx = blockIdx.x * blockDim.x + threadIdx.x;
    int stride = gridDim.x * blockDim.x;
    float term = 0.0f;
    for (int i = idx; i < N; i += stride) {
        float w0 = g_weights[2 * i], w1 = g_weights[2 * i + 1];
        float pm = g_pos[0][i], pp = g_pos[1][i];
        float sm = g_sumall[0][i], sp = g_sumall[1][i];
        float wpv = w0 * pm + w1 * pp;
        float wn = w0 * (sm - pm) + w1 * (sp - pp);
        float nei = fmaxf(g_rowsum[0][i] + g_rowsum[1][i], 1.0f);
        float ratio = wpv / (wpv + wn) / nei;
        ratio = fmaxf(ratio, 1e-10f);
        term += -logf(ratio);
    }
    __shared__ float red[256];
    red[threadIdx.x] = term;
    __syncthreads();
#pragma unroll
    for (int s = 128; s > 0; s >>= 1) {
        if (threadIdx.x < s) red[threadIdx.x] += red[threadIdx.x + s];
        __syncthreads();
    }
    if (threadIdx.x == 0) atomicAdd(&g_loss_acc, red[0]);
}

__global__ void k_finalize(float* __restrict__ out) {
    out[0] = g_loss_acc / (float)N;
}

// ---------------- launch (fork-join overlap) ----------------
extern "C" void kernel_launch(void* const* d_in, const int* in_sizes, int n_in,
                              void* d_out, int out_size) {
    const float* embF = (const float*)d_in[0];
    const float* embM = (const float*)d_in[1];
    const float* embP = (const float*)d_in[2];
    const float* FM_adj = (const float*)d_in[3];
    const float* FP_adj = (const float*)d_in[4];
    const float* W1 = (const float*)d_in[5];
    const float* b1 = (const float*)d_in[6];
    const float* W2 = (const float*)d_in[7];
    const float* b2 = (const float*)d_in[8];
    float* out = (float*)d_out;

    static cudaStream_t s1 = nullptr;
    static cudaEvent_t evZ = nullptr, evN = nullptr, evB = nullptr;
    static bool attr_set = false;
    if (!attr_set) {
        cudaStreamCreateWithFlags(&s1, cudaStreamNonBlocking);
        cudaEventCreateWithFlags(&evZ, cudaEventDisableTiming);
        cudaEventCreateWithFlags(&evN, cudaEventDisableTiming);
        cudaEventCreateWithFlags(&evB, cudaEventDisableTiming);
        cudaFuncSetAttribute(k_simsum_mma, cudaFuncAttributeMaxDynamicSharedMemorySize, SIMTC_SMEM);
        cudaFuncSetAttribute(k_mlp, cudaFuncAttributeMaxDynamicSharedMemorySize, MLP_SMEM);
        attr_set = true;
    }

    k_zero<<<(2 * N + 255) / 256, 256>>>();
    cudaEventRecord(evZ, 0);

    // side stream: adjacency scan starts immediately (needs only g_cnt zeroed)
    cudaStreamWaitEvent(s1, evZ, 0);
    k_scan<<<N, 256, 0, s1>>>(FM_adj, FP_adj);

    // main stream: normalize, then tensor-core sim sums
    k_normalize<<<dim3(N, 3), 128>>>(embF, embM, embP);
    cudaEventRecord(evN, 0);
    k_simsum_mma<<<dim3(N / 128, JSPLIT), 256, SIMTC_SMEM>>>();

    // side stream: gather (needs norm + scan), then MLP
    cudaStreamWaitEvent(s1, evN, 0);
    k_gather<<<dim3(N, 2), 128, 0, s1>>>(embM, embP);
    k_mlp<<<N / MLP_ROWS, 256, MLP_SMEM, s1>>>(W1, b1, W2, b2, out + 1);
    cudaEventRecord(evB, s1);

    cudaStreamWaitEvent(0, evB, 0);
    k_loss<<<24, 256>>>();
    k_finalize<<<1, 1>>>(out);
}